// round 13
// baseline (speedup 1.0000x reference)
#include <cuda_runtime.h>
#include <cuda_bf16.h>

// Contamination: out = 0.8*x + 0.2 * avg(valid neighbors at {-8,0,8}^2 \ {0,0})
// x: [B=8, C=32, H=512, W=512] fp32, k=8.
//
// R13 = shuffle side-columns (R4: best-ever per-warp BW; side neighbors are
// exactly +/-2 lanes, so the two 5-line unaligned side loads become 8 SHFLs
// + one 2-line edge load) + depth-2 center prefetch (R9/R10), with liveness
// trimmed to fit 36 regs @ lb(256,7) = 56 warps/SM:
//   - carried: Sprev, Scur, cN (12 floats); ctr reloaded (L1 hit)
//   - edge lanes (0,1,30,31) share ONE predicated temp 'e'
//   - shuffles per-component with scalar temps
// Warp L1 wavefronts/iter: ~14 vs R10's ~22 -> less queue-inflated latency.

namespace {

constexpr int H  = 512;
constexpr int W  = 512;
constexpr int K  = 8;
constexpr int W4 = W / 4;       // 128 float4 per row

__device__ __forceinline__ float4 f4zero() { return make_float4(0.f, 0.f, 0.f, 0.f); }

__device__ __forceinline__ float4 f4add(float4 a, float4 b) {
    return make_float4(a.x + b.x, a.y + b.y, a.z + b.z, a.w + b.w);
}

__global__ __launch_bounds__(256, 7)
void contam_kernel(const float4* __restrict__ in, float4* __restrict__ out) {
    const int lane = threadIdx.x;                     // warp spans 32 float4 cols
    const int c4   = blockIdx.x * 32 + lane;          // 0..127
    const int row0 = blockIdx.y * 32 + threadIdx.y;   // first output row (<=487)
    const int plane = blockIdx.z;

    const float4* __restrict__ pin  = in  + (size_t)plane * (H * W4);
    float4* __restrict__       pout = out + (size_t)plane * (H * W4);

    const bool hasL = (c4 >= 2);
    const bool hasR = (c4 <= W4 - 3);
    const int  nc   = 1 + (int)hasL + (int)hasR;

    // edge-lane bookkeeping: lanes 0,1 need c4-2 (outside warp), lanes 30,31
    // need c4+2. One temp 'e' serves both (disjoint lanes).
    const bool eLane = (lane < 2) ? hasL : ((lane >= 30) ? hasR : false);
    const int  eoff  = c4 + ((lane < 2) ? -2 : 2);

    // ---- prologue (direct loads; once) ----
    float4 Sprev = f4zero();
    if (row0 >= K) {
        const float4* __restrict__ r = pin + (row0 - K) * W4;
        Sprev = r[c4];
        if (hasL) Sprev = f4add(Sprev, r[c4 - 2]);
        if (hasR) Sprev = f4add(Sprev, r[c4 + 2]);
    }
    float4 Scur;
    {
        const float4* __restrict__ r = pin + row0 * W4;
        Scur = r[c4];
        if (hasL) Scur = f4add(Scur, r[c4 - 2]);
        if (hasR) Scur = f4add(Scur, r[c4 + 2]);
    }
    float4 cN = pin[(row0 + K) * W4 + c4];   // row0+K <= 495, always valid

    #pragma unroll
    for (int ry = 0; ry < 4; ry++) {
        const int h   = row0 + ry * K;
        const int rn  = h + K;
        const bool vn = (rn < H);
        const int rn2 = h + 2 * K;
        const int rn2c = (rn2 < H) ? rn2 : h;    // clamped legal address

        // ---- batched issue: ctr (L1 hit), edge temp (2 lines/warp),
        //      prefetch center of h+2K (the one true DRAM miss) ----
        const float4* __restrict__ rowN = pin + rn * W4;  // only deref'd if vn
        float4 ctr = pin[h * W4 + c4];
        float4 e   = f4zero();
        if (vn && eLane) e = rowN[eoff];
        float4 cN2 = pin[rn2c * W4 + c4];

        // ---- side columns of row rn via +/-2-lane shuffles of cN ----
        float4 Snext;
        {
            float lx, rx;
            lx = __shfl_up_sync(0xffffffffu, cN.x, 2);
            rx = __shfl_down_sync(0xffffffffu, cN.x, 2);
            if (lane < 2)  lx = e.x;
            if (lane >= 30) rx = e.x;
            Snext.x = cN.x + lx + rx;

            lx = __shfl_up_sync(0xffffffffu, cN.y, 2);
            rx = __shfl_down_sync(0xffffffffu, cN.y, 2);
            if (lane < 2)  lx = e.y;
            if (lane >= 30) rx = e.y;
            Snext.y = cN.y + lx + rx;

            lx = __shfl_up_sync(0xffffffffu, cN.z, 2);
            rx = __shfl_down_sync(0xffffffffu, cN.z, 2);
            if (lane < 2)  lx = e.z;
            if (lane >= 30) rx = e.z;
            Snext.z = cN.z + lx + rx;

            lx = __shfl_up_sync(0xffffffffu, cN.w, 2);
            rx = __shfl_down_sync(0xffffffffu, cN.w, 2);
            if (lane < 2)  lx = e.w;
            if (lane >= 30) rx = e.w;
            Snext.w = cN.w + lx + rx;
        }
        if (!vn) Snext = f4zero();   // warp-uniform

        const int nr = 1 + (int)(h >= K) + (int)vn;
        // count = nr*nc - 1 in {3,5,8}  <=>  nr+nc in {4,5,6}
        const int s  = nr + nc;
        const float scale = (s == 6) ? 0.025f
                          : (s == 5) ? 0.04f
                                     : 0.066666667f;

        float4 acc = f4add(f4add(Sprev, Scur), Snext);

        float4 o;
        o.x = 0.8f * ctr.x + scale * (acc.x - ctr.x);
        o.y = 0.8f * ctr.y + scale * (acc.y - ctr.y);
        o.z = 0.8f * ctr.z + scale * (acc.z - ctr.z);
        o.w = 0.8f * ctr.w + scale * (acc.w - ctr.w);

        __stcs(&pout[h * W4 + c4], o);

        Sprev = Scur;
        Scur  = Snext;
        cN    = cN2;
    }
}

} // namespace

extern "C" void kernel_launch(void* const* d_in, const int* in_sizes, int n_in,
                              void* d_out, int out_size) {
    const float4* x = (const float4*)d_in[0];
    float4* out = (float4*)d_out;

    const int planes = in_sizes[0] / (H * W);   // 256

    dim3 block(32, 8, 1);
    dim3 grid(W4 / 32, H / 32, planes);         // (4, 16, 256)
    contam_kernel<<<grid, block>>>(x, out);
}

// round 14
// speedup vs baseline: 1.2558x; 1.2558x over previous
#include <cuda_runtime.h>
#include <cuda.h>
#include <cuda_bf16.h>

// Contamination: out = 0.8*x + 0.2 * avg(valid neighbors at {-8,0,8}^2 \ {0,0})
// x: [B=8, C=32, H=512, W=512] fp32, k=8.
//
// R14: TMA-staged tiles. 13 rounds of LDG-path scheduling plateaued at
// ~5.3TB/s: achieved BW was always gated by per-warp load latency x occupancy,
// and every fix cost registers. This moves ALL input loading to one
// UTMALDG per CTA (144x48-float halo tile -> smem, OOB zero-filled so image
// borders need no value logic; counts stay positional). Warps only do cheap
// conflict-free LDS.128 rolling sums + STG stores. ~8 CTAs/SM each with a
// 27.6KB bulk load in flight decouples DRAM saturation from warp MLP.
// Fallback: proven R10 LDG kernel if cuTensorMapEncodeTiled is unavailable.

namespace {

constexpr int H  = 512;
constexpr int W  = 512;
constexpr int K  = 8;
constexpr int W4 = W / 4;           // 128 float4 per row

// TMA tile: 144 floats (128 + 2*8 halo) x 48 rows (32 + 2*8 halo)
constexpr int TC  = 144;            // floats per tile row
constexpr int TC4 = TC / 4;         // 36 float4 per tile row
constexpr int TR  = 48;             // tile rows
constexpr int TILE_BYTES = TC * TR * 4;  // 27648

__device__ __forceinline__ float4 f4zero() { return make_float4(0.f, 0.f, 0.f, 0.f); }

__device__ __forceinline__ float4 f4add(float4 a, float4 b) {
    return make_float4(a.x + b.x, a.y + b.y, a.z + b.z, a.w + b.w);
}

__device__ __forceinline__ void mbar_wait_parity(uint32_t mbar, uint32_t parity) {
    asm volatile(
        "{\n\t"
        ".reg .pred P1;\n\t"
        "WAIT_LOOP_%=:\n\t"
        "mbarrier.try_wait.parity.acquire.cta.shared::cta.b64 P1, [%0], %1, 0x989680;\n\t"
        "@P1 bra.uni WAIT_DONE_%=;\n\t"
        "bra.uni WAIT_LOOP_%=;\n\t"
        "WAIT_DONE_%=:\n\t"
        "}"
        :: "r"(mbar), "r"(parity) : "memory");
}

// row sum (3 float4 cols) + center from the smem tile
__device__ __forceinline__ void row_sum(const float4* __restrict__ t, int lr, int c4,
                                        float4& sum, float4& ctr) {
    const float4* __restrict__ r = t + lr * TC4;
    float4 a = r[c4];
    float4 b = r[c4 + 2];
    float4 c = r[c4 + 4];
    ctr = b;
    sum = f4add(f4add(a, b), c);
}

__global__ __launch_bounds__(256, 8)
void contam_tma_kernel(const __grid_constant__ CUtensorMap tmap,
                       float4* __restrict__ out) {
    __shared__ alignas(128) float tile_f[TR * TC];
    __shared__ uint64_t mbar;

    const int c4  = threadIdx.x;                    // 0..31
    const int ty  = threadIdx.y;                    // 0..7
    const int tid = ty * 32 + c4;

    const uint32_t mbar_addr = (uint32_t)__cvta_generic_to_shared(&mbar);
    const uint32_t tile_addr = (uint32_t)__cvta_generic_to_shared(tile_f);

    if (tid == 0) {
        asm volatile("mbarrier.init.shared.b64 [%0], %1;"
                     :: "r"(mbar_addr), "r"(1) : "memory");
    }
    __syncthreads();

    if (tid == 0) {
        asm volatile("mbarrier.arrive.expect_tx.shared.b64 _, [%0], %1;"
                     :: "r"(mbar_addr), "r"((uint32_t)TILE_BYTES) : "memory");
        const int x0 = blockIdx.x * 128 - K;        // float coord (OOB zero-filled)
        const int y0 = blockIdx.y * 32 - K;         // row coord
        const int z  = blockIdx.z;                  // plane
        asm volatile(
            "cp.async.bulk.tensor.3d.shared::cta.global.tile.mbarrier::complete_tx::bytes "
            "[%0], [%1, {%2, %3, %4}], [%5];"
            :: "r"(tile_addr), "l"(&tmap), "r"(x0), "r"(y0), "r"(z), "r"(mbar_addr)
            : "memory");
    }

    mbar_wait_parity(mbar_addr, 0);

    const float4* __restrict__ t = reinterpret_cast<const float4*>(tile_f);
    float4* __restrict__ pout = out + (size_t)blockIdx.z * (H * W4);

    const int c4g = blockIdx.x * 32 + c4;           // global float4 column
    const int nc  = 1 + (int)(c4g >= 2) + (int)(c4g <= W4 - 3);

    // rolling sums over tile-local rows; OOB halo values are zeros, so no
    // value-side validity logic is needed anywhere.
    float4 Sprev, Scur, Ccur, dummy;
    row_sum(t, ty,     c4, Sprev, dummy);           // global row h-8
    row_sum(t, ty + 8, c4, Scur,  Ccur);            // global row h

    #pragma unroll
    for (int ry = 0; ry < 4; ry++) {
        const int lr = ty + 8 + ry * 8;             // tile-local row of output
        const int h  = blockIdx.y * 32 + ty + ry * 8;

        float4 Snext, Cnext;
        row_sum(t, lr + 8, c4, Snext, Cnext);       // global row h+8 (<=47 local)

        const int nr = 1 + (int)(h >= K) + (int)(h < H - K);
        // count = nr*nc - 1 in {3,5,8}  <=>  nr+nc in {4,5,6}
        const int s  = nr + nc;
        const float scale = (s == 6) ? 0.025f
                          : (s == 5) ? 0.04f
                                     : 0.066666667f;
        const float a = 0.8f - scale;

        // acc includes the center: out = (0.8-scale)*ctr + scale*acc
        float4 acc = f4add(f4add(Sprev, Scur), Snext);

        float4 o;
        o.x = a * Ccur.x + scale * acc.x;
        o.y = a * Ccur.y + scale * acc.y;
        o.z = a * Ccur.z + scale * acc.z;
        o.w = a * Ccur.w + scale * acc.w;

        __stcs(&pout[h * W4 + c4g], o);

        Sprev = Scur;
        Scur  = Snext;
        Ccur  = Cnext;
    }
}

// ---------------- fallback: proven R10 LDG kernel (96.6us) ----------------

__global__ __launch_bounds__(256, 8)
void contam_ldg_kernel(const float4* __restrict__ in, float4* __restrict__ out) {
    const int c4   = blockIdx.x * 32 + threadIdx.x;
    const int row0 = blockIdx.y * 32 + threadIdx.y;
    const int plane = blockIdx.z;

    const float4* __restrict__ pin  = in  + (size_t)plane * (H * W4);
    float4* __restrict__       pout = out + (size_t)plane * (H * W4);

    const bool hasL = (c4 >= 2);
    const bool hasR = (c4 <= W4 - 3);
    const int  nc   = 1 + (int)hasL + (int)hasR;

    float4 Sprev = f4zero();
    if (row0 >= K) {
        const float4* __restrict__ r = pin + (row0 - K) * W4;
        Sprev = r[c4];
        if (hasL) Sprev = f4add(Sprev, r[c4 - 2]);
        if (hasR) Sprev = f4add(Sprev, r[c4 + 2]);
    }
    float4 Scur;
    {
        const float4* __restrict__ r = pin + row0 * W4;
        Scur = r[c4];
        if (hasL) Scur = f4add(Scur, r[c4 - 2]);
        if (hasR) Scur = f4add(Scur, r[c4 + 2]);
    }
    float4 cN = pin[(row0 + K) * W4 + c4];

    #pragma unroll
    for (int ry = 0; ry < 4; ry++) {
        const int h   = row0 + ry * K;
        const int rn  = h + K;
        const bool vn = (rn < H);
        const int rn2 = h + 2 * K;
        const int rn2c = (rn2 < H) ? rn2 : h;

        const float4* __restrict__ rowC = pin + h * W4;
        const float4* __restrict__ rowN = pin + (vn ? rn : h) * W4;
        float4 ctr = rowC[c4];
        float4 s0  = hasL ? rowN[c4 - 2] : f4zero();
        float4 s2  = hasR ? rowN[c4 + 2] : f4zero();
        float4 cN2 = pin[rn2c * W4 + c4];

        float4 Snext = vn ? f4add(f4add(cN, s0), s2) : f4zero();

        const int nr = 1 + (int)(h >= K) + (int)vn;
        const int s  = nr + nc;
        const float scale = (s == 6) ? 0.025f
                          : (s == 5) ? 0.04f
                                     : 0.066666667f;

        float4 acc = f4add(f4add(Sprev, Scur), Snext);

        float4 o;
        o.x = 0.8f * ctr.x + scale * (acc.x - ctr.x);
        o.y = 0.8f * ctr.y + scale * (acc.y - ctr.y);
        o.z = 0.8f * ctr.z + scale * (acc.z - ctr.z);
        o.w = 0.8f * ctr.w + scale * (acc.w - ctr.w);

        __stcs(&pout[h * W4 + c4], o);

        Sprev = Scur;
        Scur  = Snext;
        cN    = cN2;
    }
}

typedef CUresult (CUDAAPI *PFN_encodeTiled_local)(
    CUtensorMap*, CUtensorMapDataType, cuuint32_t, void*,
    const cuuint64_t*, const cuuint64_t*, const cuuint32_t*, const cuuint32_t*,
    CUtensorMapInterleave, CUtensorMapSwizzle, CUtensorMapL2promotion,
    CUtensorMapFloatOOBfill);

} // namespace

extern "C" void kernel_launch(void* const* d_in, const int* in_sizes, int n_in,
                              void* d_out, int out_size) {
    const float4* x = (const float4*)d_in[0];
    float4* out = (float4*)d_out;
    const int planes = in_sizes[0] / (H * W);   // 256

    // --- build tensor map host-side (pure host work; graph-capture safe) ---
    PFN_encodeTiled_local encode = nullptr;
    cudaDriverEntryPointQueryResult qres = cudaDriverEntryPointSymbolNotFound;
#if CUDART_VERSION >= 12050
    cudaGetDriverEntryPointByVersion("cuTensorMapEncodeTiled", (void**)&encode,
                                     12000, cudaEnableDefault, &qres);
#else
    cudaGetDriverEntryPoint("cuTensorMapEncodeTiled", (void**)&encode,
                            cudaEnableDefault, &qres);
#endif

    bool tma_ok = false;
    CUtensorMap tmap;
    if (encode && qres == cudaDriverEntryPointSuccess) {
        cuuint64_t dims[3]    = {(cuuint64_t)W, (cuuint64_t)H, (cuuint64_t)planes};
        cuuint64_t strides[2] = {(cuuint64_t)W * 4, (cuuint64_t)W * H * 4};
        cuuint32_t box[3]     = {TC, TR, 1};
        cuuint32_t estr[3]    = {1, 1, 1};
        CUresult r = encode(&tmap, CU_TENSOR_MAP_DATA_TYPE_FLOAT32, 3,
                            (void*)x, dims, strides, box, estr,
                            CU_TENSOR_MAP_INTERLEAVE_NONE,
                            CU_TENSOR_MAP_SWIZZLE_NONE,
                            CU_TENSOR_MAP_L2_PROMOTION_L2_128B,
                            CU_TENSOR_MAP_FLOAT_OOB_FILL_NONE);
        tma_ok = (r == CUDA_SUCCESS);
    }

    dim3 block(32, 8, 1);
    dim3 grid(W4 / 32, H / 32, planes);         // (4, 16, 256)

    if (tma_ok) {
        contam_tma_kernel<<<grid, block>>>(tmap, out);
    } else {
        contam_ldg_kernel<<<grid, block>>>(x, out);
    }
}

// round 15
// speedup vs baseline: 1.3294x; 1.0586x over previous
#include <cuda_runtime.h>
#include <cuda_bf16.h>

// Contamination: out = 0.8*x + 0.2 * avg(valid neighbors at {-8,0,8}^2 \ {0,0})
// x: [B=8, C=32, H=512, W=512] fp32, k=8.
//
// R15 = R10's exact loop body (depth-2 center prefetch, batched loads,
// streaming stores, 32 regs, lb(256,8)) but each CTA MARCHES down a 128-row
// group (16 iterations) instead of owning a 32-row tile:
//   - prologue (6 loads) amortized over 16 outputs instead of 4
//   - vertical halo refetch: 50% of reads -> 1.6% (L1/L2 wavefront cut)
//   - rolling working set ~3 rows/CTA -> tiny concurrent L2 footprint
// L1 ops/output 5.5 -> 4.4 at ZERO register/occupancy cost — the combination
// every prior failed restructure lacked.

namespace {

constexpr int H  = 512;
constexpr int W  = 512;
constexpr int K  = 8;
constexpr int W4 = W / 4;        // 128 float4 per row
constexpr int GROUP_ROWS = 128;  // rows per CTA
constexpr int ITERS = GROUP_ROWS / 8;  // 16 iterations per thread

__device__ __forceinline__ float4 f4zero() { return make_float4(0.f, 0.f, 0.f, 0.f); }

__device__ __forceinline__ float4 f4add(float4 a, float4 b) {
    return make_float4(a.x + b.x, a.y + b.y, a.z + b.z, a.w + b.w);
}

__global__ __launch_bounds__(256, 8)
void contam_kernel(const float4* __restrict__ in, float4* __restrict__ out) {
    const int c4   = blockIdx.x * 32 + threadIdx.x;        // float4 column, 0..127
    const int row0 = blockIdx.y * GROUP_ROWS + threadIdx.y; // first output row
    const int plane = blockIdx.z;

    const float4* __restrict__ pin  = in  + (size_t)plane * (H * W4);
    float4* __restrict__       pout = out + (size_t)plane * (H * W4);

    const bool hasL = (c4 >= 2);
    const bool hasR = (c4 <= W4 - 3);
    const int  nc   = 1 + (int)hasL + (int)hasR;

    // ---- prologue: Sprev (row0-K sum), Scur (row0 sum), cN = center(row0+K) ----
    float4 Sprev = f4zero();
    if (row0 >= K) {
        const float4* __restrict__ r = pin + (row0 - K) * W4;
        Sprev = r[c4];
        if (hasL) Sprev = f4add(Sprev, r[c4 - 2]);
        if (hasR) Sprev = f4add(Sprev, r[c4 + 2]);
    }
    float4 Scur;
    {
        const float4* __restrict__ r = pin + row0 * W4;
        Scur = r[c4];
        if (hasL) Scur = f4add(Scur, r[c4 - 2]);
        if (hasR) Scur = f4add(Scur, r[c4 + 2]);
    }
    float4 cN = pin[(row0 + K) * W4 + c4];   // row0+K <= 391+8+... <= 503: valid

    #pragma unroll 4
    for (int ry = 0; ry < ITERS; ry++) {
        const int h   = row0 + ry * K;
        const int rn  = h + K;
        const bool vn = (rn < H);
        const int rn2 = h + 2 * K;
        const int rn2c = (rn2 < H) ? rn2 : h;   // clamped legal address

        // ---- batched issue: ctr (L1 hit), sides of row rn (mostly L1 hits on
        //      the line prefetched last iteration), prefetch center h+2K ----
        const float4* __restrict__ rowC = pin + h * W4;
        const float4* __restrict__ rowN = pin + (vn ? rn : h) * W4;
        float4 ctr = rowC[c4];
        float4 s0  = hasL ? rowN[c4 - 2] : f4zero();
        float4 s2  = hasR ? rowN[c4 + 2] : f4zero();
        float4 cN2 = pin[rn2c * W4 + c4];

        float4 Snext = vn ? f4add(f4add(cN, s0), s2) : f4zero();

        const int nr = 1 + (int)(h >= K) + (int)vn;
        // count = nr*nc - 1 in {3,5,8}  <=>  nr+nc in {4,5,6}
        const int s  = nr + nc;
        const float scale = (s == 6) ? 0.025f
                          : (s == 5) ? 0.04f
                                     : 0.066666667f;

        float4 acc = f4add(f4add(Sprev, Scur), Snext);

        float4 o;
        o.x = 0.8f * ctr.x + scale * (acc.x - ctr.x);
        o.y = 0.8f * ctr.y + scale * (acc.y - ctr.y);
        o.z = 0.8f * ctr.z + scale * (acc.z - ctr.z);
        o.w = 0.8f * ctr.w + scale * (acc.w - ctr.w);

        __stcs(&pout[h * W4 + c4], o);

        Sprev = Scur;
        Scur  = Snext;
        cN    = cN2;
    }
}

} // namespace

extern "C" void kernel_launch(void* const* d_in, const int* in_sizes, int n_in,
                              void* d_out, int out_size) {
    const float4* x = (const float4*)d_in[0];
    float4* out = (float4*)d_out;

    const int planes = in_sizes[0] / (H * W);   // 256

    dim3 block(32, 8, 1);
    dim3 grid(W4 / 32, H / GROUP_ROWS, planes); // (4, 4, 256) = 4096 CTAs
    contam_kernel<<<grid, block>>>(x, out);
}

// round 16
// speedup vs baseline: 1.3795x; 1.0376x over previous
#include <cuda_runtime.h>
#include <cuda_bf16.h>

// Contamination: out = 0.8*x + 0.2 * avg(valid neighbors at {-8,0,8}^2 \ {0,0})
// x: [B=8, C=32, H=512, W=512] fp32, k=8.
//
// R16 = R15's column-march (validated: L1 59%, DRAM 69.6% — both best-ever)
// at the wave-friendly granularity. R15's 4096 CTAs = 3.46 waves of 1184
// rounded to 4 (+15% tail) and ate the win; GROUP_ROWS=64 gives 8192 CTAs =
// 6.92 waves (last wave 98.8% full, +1.2%), while keeping most of the
// prologue amortization (L1 ops/output 4.75 vs R10's 5.5). Same loop body,
// 32 regs, lb(256,8), depth-2 center prefetch, streaming stores.

namespace {

constexpr int H  = 512;
constexpr int W  = 512;
constexpr int K  = 8;
constexpr int W4 = W / 4;        // 128 float4 per row
constexpr int GROUP_ROWS = 64;   // rows per CTA
constexpr int ITERS = GROUP_ROWS / 8;  // 8 iterations per thread

__device__ __forceinline__ float4 f4zero() { return make_float4(0.f, 0.f, 0.f, 0.f); }

__device__ __forceinline__ float4 f4add(float4 a, float4 b) {
    return make_float4(a.x + b.x, a.y + b.y, a.z + b.z, a.w + b.w);
}

__global__ __launch_bounds__(256, 8)
void contam_kernel(const float4* __restrict__ in, float4* __restrict__ out) {
    const int c4   = blockIdx.x * 32 + threadIdx.x;          // float4 column, 0..127
    const int row0 = blockIdx.y * GROUP_ROWS + threadIdx.y;  // first output row
    const int plane = blockIdx.z;

    const float4* __restrict__ pin  = in  + (size_t)plane * (H * W4);
    float4* __restrict__       pout = out + (size_t)plane * (H * W4);

    const bool hasL = (c4 >= 2);
    const bool hasR = (c4 <= W4 - 3);
    const int  nc   = 1 + (int)hasL + (int)hasR;

    // ---- prologue: Sprev (row0-K sum), Scur (row0 sum), cN = center(row0+K) ----
    float4 Sprev = f4zero();
    if (row0 >= K) {
        const float4* __restrict__ r = pin + (row0 - K) * W4;
        Sprev = r[c4];
        if (hasL) Sprev = f4add(Sprev, r[c4 - 2]);
        if (hasR) Sprev = f4add(Sprev, r[c4 + 2]);
    }
    float4 Scur;
    {
        const float4* __restrict__ r = pin + row0 * W4;
        Scur = r[c4];
        if (hasL) Scur = f4add(Scur, r[c4 - 2]);
        if (hasR) Scur = f4add(Scur, r[c4 + 2]);
    }
    float4 cN = pin[(row0 + K) * W4 + c4];   // row0+K <= 503: always valid

    #pragma unroll 4
    for (int ry = 0; ry < ITERS; ry++) {
        const int h   = row0 + ry * K;
        const int rn  = h + K;
        const bool vn = (rn < H);
        const int rn2 = h + 2 * K;
        const int rn2c = (rn2 < H) ? rn2 : h;   // clamped legal address

        // ---- batched issue: ctr (L1 hit), sides of row rn (mostly L1 hits on
        //      the line prefetched last iteration), prefetch center h+2K ----
        const float4* __restrict__ rowC = pin + h * W4;
        const float4* __restrict__ rowN = pin + (vn ? rn : h) * W4;
        float4 ctr = rowC[c4];
        float4 s0  = hasL ? rowN[c4 - 2] : f4zero();
        float4 s2  = hasR ? rowN[c4 + 2] : f4zero();
        float4 cN2 = pin[rn2c * W4 + c4];

        float4 Snext = vn ? f4add(f4add(cN, s0), s2) : f4zero();

        const int nr = 1 + (int)(h >= K) + (int)vn;
        // count = nr*nc - 1 in {3,5,8}  <=>  nr+nc in {4,5,6}
        const int s  = nr + nc;
        const float scale = (s == 6) ? 0.025f
                          : (s == 5) ? 0.04f
                                     : 0.066666667f;

        float4 acc = f4add(f4add(Sprev, Scur), Snext);

        float4 o;
        o.x = 0.8f * ctr.x + scale * (acc.x - ctr.x);
        o.y = 0.8f * ctr.y + scale * (acc.y - ctr.y);
        o.z = 0.8f * ctr.z + scale * (acc.z - ctr.z);
        o.w = 0.8f * ctr.w + scale * (acc.w - ctr.w);

        __stcs(&pout[h * W4 + c4], o);

        Sprev = Scur;
        Scur  = Snext;
        cN    = cN2;
    }
}

} // namespace

extern "C" void kernel_launch(void* const* d_in, const int* in_sizes, int n_in,
                              void* d_out, int out_size) {
    const float4* x = (const float4*)d_in[0];
    float4* out = (float4*)d_out;

    const int planes = in_sizes[0] / (H * W);   // 256

    dim3 block(32, 8, 1);
    dim3 grid(W4 / 32, H / GROUP_ROWS, planes); // (4, 8, 256) = 8192 CTAs
    contam_kernel<<<grid, block>>>(x, out);
}